// round 5
// baseline (speedup 1.0000x reference)
#include <cuda_runtime.h>

#define D 128
#define NMAX 50048
#define EMAX 800000

// ---------------- scratch (static device allocations; no cudaMalloc) --------
__device__ float g_q[(size_t)NMAX * D];
__device__ float g_k[(size_t)NMAX * D];
__device__ float g_v[(size_t)NMAX * D];
__device__ float g_agg[(size_t)NMAX * D];
__device__ float g_WT[4 * D * D];     // transposed weights: WT[k*128 + j] = W[j*128 + k]
__device__ int   g_cnt[NMAX];
__device__ int   g_offs[NMAX + 1];
__device__ int   g_cur[NMAX];
__device__ int   g_src[EMAX];
__device__ int   g_is64;              // 1 if edge_index is int64, 0 if int32

// ---------------- edge dtype detection --------------------------------------
// JAX with x64 disabled silently coerces jnp.int64 -> int32, so the edge_index
// buffer may be either width. Reading int32 data as int64 gives lo + hi*2^32
// which is >= 2^32 (>= NMAX) unless hi==0 (p ~ 1/50000 per sample). 16 samples
// all in-range => genuinely int64.
__global__ void detect_kernel(const void* ei, int e) {
    const long long* p = (const long long*)ei;
    int lim = (2 * e < 16) ? 2 * e : 16;
    int ok = 1;
    for (int i = 0; i < lim; ++i) {
        long long v = p[i];
        if (v < 0 || v >= NMAX) { ok = 0; break; }
    }
    g_is64 = ok;
}

__device__ __forceinline__ int load_edge(const void* ei, size_t idx, int is64) {
    if (is64) return (int)((const long long*)ei)[idx];
    return ((const int*)ei)[idx];
}

// ---------------- weight transpose -----------------------------------------
__global__ void transpose4_kernel(const float* __restrict__ W0,
                                  const float* __restrict__ W1,
                                  const float* __restrict__ W2,
                                  const float* __restrict__ W3) {
    const float* Ws[4] = {W0, W1, W2, W3};
    int m   = blockIdx.y;
    int idx = blockIdx.x * blockDim.x + threadIdx.x;   // 0..16383
    if (idx < D * D) {
        int j = idx >> 7;      // row of W
        int k = idx & 127;     // col of W
        g_WT[m * D * D + k * D + j] = Ws[m][idx];
    }
}

// ---------------- SGEMM: C[M x 128] = A[M x 128] @ W^T + bias ---------------
// 128x128 block tile, BK=8, 8x8 microtile, 256 threads.
__global__ __launch_bounds__(256)
void sgemm128_kernel(const float* Aext, int asel,
                     int wsel, const float* __restrict__ bias,
                     float* Cext, int csel, int M) {
    __shared__ float As[8][132];   // padded: conflict-free transposed stores
    __shared__ float Bs[8][128];

    const float* A  = asel ? g_agg : Aext;
    const float* Bt = g_WT + wsel * D * D;
    float* C = (csel == 0) ? g_q : (csel == 1) ? g_k : (csel == 2) ? g_v : Cext;

    const int tid       = threadIdx.x;
    const int block_row = blockIdx.x * 128;
    const int tx = tid & 15;   // col group: cols [tx*8, tx*8+8)
    const int ty = tid >> 4;   // row group: rows [ty*8, ty*8+8)

    const int arow = tid >> 1;          // 0..127
    const int acol = (tid & 1) << 2;    // 0 or 4
    const int brow = tid >> 5;          // 0..7
    const int bcol = (tid & 31) << 2;   // 0..124

    float acc[8][8];
#pragma unroll
    for (int i = 0; i < 8; i++)
#pragma unroll
        for (int j = 0; j < 8; j++) acc[i][j] = 0.f;

    for (int k0 = 0; k0 < D; k0 += 8) {
        float4 av;
        int gr = block_row + arow;
        if (gr < M) av = *(const float4*)(A + (size_t)gr * D + k0 + acol);
        else        av = make_float4(0.f, 0.f, 0.f, 0.f);
        As[acol + 0][arow] = av.x;
        As[acol + 1][arow] = av.y;
        As[acol + 2][arow] = av.z;
        As[acol + 3][arow] = av.w;

        float4 bv = *(const float4*)(Bt + (size_t)(k0 + brow) * D + bcol);
        *(float4*)&Bs[brow][bcol] = bv;
        __syncthreads();

#pragma unroll
        for (int kk = 0; kk < 8; kk++) {
            float af[8], bf[8];
            *(float4*)&af[0] = *(const float4*)&As[kk][ty * 8];
            *(float4*)&af[4] = *(const float4*)&As[kk][ty * 8 + 4];
            *(float4*)&bf[0] = *(const float4*)&Bs[kk][tx * 8];
            *(float4*)&bf[4] = *(const float4*)&Bs[kk][tx * 8 + 4];
#pragma unroll
            for (int i = 0; i < 8; i++)
#pragma unroll
                for (int j = 0; j < 8; j++)
                    acc[i][j] += af[i] * bf[j];
        }
        __syncthreads();
    }

#pragma unroll
    for (int i = 0; i < 8; i++) {
        int row = block_row + ty * 8 + i;
        if (row < M) {
#pragma unroll
            for (int j = 0; j < 8; j += 4) {
                int col = tx * 8 + j;
                float4 o;
                o.x = acc[i][j + 0] + bias[col + 0];
                o.y = acc[i][j + 1] + bias[col + 1];
                o.z = acc[i][j + 2] + bias[col + 2];
                o.w = acc[i][j + 3] + bias[col + 3];
                *(float4*)(C + (size_t)row * D + col) = o;
            }
        }
    }
}

// ---------------- CSR build --------------------------------------------------
__global__ void zero_cnt_kernel(int n) {
    for (int i = blockIdx.x * blockDim.x + threadIdx.x; i < n; i += gridDim.x * blockDim.x)
        g_cnt[i] = 0;
}

__global__ void hist_kernel(const void* __restrict__ ei, int e, int n) {
    int is64 = g_is64;
    for (int idx = blockIdx.x * blockDim.x + threadIdx.x; idx < e; idx += gridDim.x * blockDim.x) {
        int c = load_edge(ei, 2 * (size_t)idx + 1, is64);
        if ((unsigned)c < (unsigned)n) atomicAdd(&g_cnt[c], 1);
    }
}

// single-block exclusive scan of g_cnt -> g_offs (and g_cur copy). 1024 threads.
__global__ void scan_kernel(int n) {
    __shared__ int warpsum[32];
    int tid  = threadIdx.x;
    int lane = tid & 31;
    int wid  = tid >> 5;
    int carry = 0;
    for (int base = 0; base < n; base += 1024) {
        int i = base + tid;
        int x = (i < n) ? g_cnt[i] : 0;
        int s = x;
#pragma unroll
        for (int off = 1; off < 32; off <<= 1) {
            int t2 = __shfl_up_sync(0xffffffffu, s, off);
            if (lane >= off) s += t2;
        }
        if (lane == 31) warpsum[wid] = s;
        __syncthreads();
        if (wid == 0) {
            int ws = warpsum[lane];
#pragma unroll
            for (int off = 1; off < 32; off <<= 1) {
                int t2 = __shfl_up_sync(0xffffffffu, ws, off);
                if (lane >= off) ws += t2;
            }
            warpsum[lane] = ws;
        }
        __syncthreads();
        int prefix = (wid > 0) ? warpsum[wid - 1] : 0;
        int excl   = s + prefix - x;
        if (i < n) {
            g_offs[i] = carry + excl;
            g_cur[i]  = carry + excl;
        }
        int total = warpsum[31];
        __syncthreads();
        carry += total;
    }
    if (tid == 0) g_offs[n] = carry;
}

__global__ void scatter_kernel(const void* __restrict__ ei, int e, int n) {
    int is64 = g_is64;
    for (int idx = blockIdx.x * blockDim.x + threadIdx.x; idx < e; idx += gridDim.x * blockDim.x) {
        int r = load_edge(ei, 2 * (size_t)idx + 0, is64);
        int c = load_edge(ei, 2 * (size_t)idx + 1, is64);
        if ((unsigned)c < (unsigned)n && (unsigned)r < (unsigned)n) {
            int pos = atomicAdd(&g_cur[c], 1);
            if ((unsigned)pos < (unsigned)EMAX) g_src[pos] = r;
        }
    }
}

// ---------------- fused per-node attention (online softmax) ------------------
// One block of 128 threads per destination node. Thread t owns feature dim t
// (head = t/16, dim-in-head = t%16). Online softmax with implicit logit 0
// (smax = max(segmax, 0); denom includes exp(-smax)): init m=0, l=1.
__global__ __launch_bounds__(128)
void attn_kernel() {
    int node = blockIdx.x;
    int t    = threadIdx.x;

    float qt  = g_q[(size_t)node * D + t] * 0.25f;   // 1/sqrt(HD=16)
    int beg = g_offs[node];
    int end = g_offs[node + 1];

    float m = 0.f, l = 1.f, acc = 0.f;
    int r = (beg < end) ? g_src[beg] : 0;
    for (int j = beg; j < end; ++j) {
        float kt = g_k[(size_t)r * D + t];
        float vt = g_v[(size_t)r * D + t];
        int rn = (j + 1 < end) ? g_src[j + 1] : 0;

        float p = qt * kt;
        p += __shfl_xor_sync(0xffffffffu, p, 8);
        p += __shfl_xor_sync(0xffffffffu, p, 4);
        p += __shfl_xor_sync(0xffffffffu, p, 2);
        p += __shfl_xor_sync(0xffffffffu, p, 1);
        // p = score for this edge & this thread's head (same on all 16 lanes)

        float nm = fmaxf(m, p);
        float sc = __expf(m - nm);
        float pe = __expf(p - nm);
        l   = l * sc + pe;
        acc = acc * sc + pe * vt;
        m   = nm;
        r   = rn;
    }

    float deg = (float)(end - beg);
    g_agg[(size_t)node * D + t] = acc / (l * fmaxf(deg, 1.f));
}

// ---------------- launch -----------------------------------------------------
extern "C" void kernel_launch(void* const* d_in, const int* in_sizes, int n_in,
                              void* d_out, int out_size) {
    const float* feats = (const float*)d_in[0];
    const void*  ei    = d_in[1];
    const float* Wq = (const float*)d_in[2];
    const float* bq = (const float*)d_in[3];
    const float* Wk = (const float*)d_in[4];
    const float* bk = (const float*)d_in[5];
    const float* Wv = (const float*)d_in[6];
    const float* bv = (const float*)d_in[7];
    const float* Wo = (const float*)d_in[8];
    const float* bo = (const float*)d_in[9];
    float* out = (float*)d_out;

    int n = in_sizes[0] / D;
    int e = in_sizes[1] / 2;
    if (n > NMAX || e > EMAX || n <= 0) return;

    // 0) detect edge_index dtype (int32 vs int64)
    detect_kernel<<<1, 1>>>(ei, e);

    // 1) transpose the four weight matrices
    transpose4_kernel<<<dim3(64, 4), 256>>>(Wq, Wk, Wv, Wo);

    // 2) Q/K/V projections
    int gblocks = (n + 127) / 128;
    sgemm128_kernel<<<gblocks, 256>>>(feats, 0, 0, bq, nullptr, 0, n);
    sgemm128_kernel<<<gblocks, 256>>>(feats, 0, 1, bk, nullptr, 1, n);
    sgemm128_kernel<<<gblocks, 256>>>(feats, 0, 2, bv, nullptr, 2, n);

    // 3) CSR by destination
    zero_cnt_kernel<<<(n + 255) / 256, 256>>>(n);
    hist_kernel<<<(e + 255) / 256, 256>>>(ei, e, n);
    scan_kernel<<<1, 1024>>>(n);
    scatter_kernel<<<(e + 255) / 256, 256>>>(ei, e, n);

    // 4) fused edge softmax + aggregation (one block per node)
    attn_kernel<<<n, 128>>>();

    // 5) output projection -> d_out
    sgemm128_kernel<<<gblocks, 256>>>(nullptr, 1, 3, bo, out, 3, n);
}

// round 10
// speedup vs baseline: 1.1480x; 1.1480x over previous
#include <cuda_runtime.h>
#include <cstdint>

#define D 128
#define NMAX 50048
#define EMAX 800000

// ---------------- scratch (static device allocations; no cudaMalloc) --------
__device__ float g_q[(size_t)NMAX * D];
__device__ float g_k[(size_t)NMAX * D];
__device__ float g_v[(size_t)NMAX * D];
__device__ float g_agg[(size_t)NMAX * D];
__device__ float g_WT[4 * D * D];     // transposed weights: WT[k*128 + j] = W[j*128 + k]
__device__ int   g_cnt[NMAX];
__device__ int   g_offs[NMAX + 1];
__device__ int   g_cur[NMAX];
__device__ int   g_src[EMAX];
__device__ int   g_is64;

// ---------------- packed f32x2 helpers (base sm_100-family ISA) -------------
__device__ __forceinline__ unsigned long long dup2(float v) {
    unsigned long long u;
    asm("mov.b64 %0, {%1, %1};" : "=l"(u) : "f"(v));
    return u;
}
__device__ __forceinline__ void ffma2(unsigned long long& d,
                                      unsigned long long a,
                                      unsigned long long b) {
    asm("fma.rn.f32x2 %0, %1, %2, %0;" : "+l"(d) : "l"(a), "l"(b));
}
__device__ __forceinline__ float2 u2f(unsigned long long u) {
    float2 f;
    asm("mov.b64 {%0, %1}, %2;" : "=f"(f.x), "=f"(f.y) : "l"(u));
    return f;
}

// ---------------- edge dtype detection --------------------------------------
// JAX with x64 disabled silently coerces jnp.int64 -> int32; detect width.
__global__ void detect_kernel(const void* ei, int e) {
    const long long* p = (const long long*)ei;
    int lim = (2 * e < 16) ? 2 * e : 16;
    int ok = 1;
    for (int i = 0; i < lim; ++i) {
        long long v = p[i];
        if (v < 0 || v >= NMAX) { ok = 0; break; }
    }
    g_is64 = ok;
}
__device__ __forceinline__ int load_edge(const void* ei, size_t idx, int is64) {
    if (is64) return (int)((const long long*)ei)[idx];
    return ((const int*)ei)[idx];
}

// ---------------- weight transpose -----------------------------------------
__global__ void transpose4_kernel(const float* __restrict__ W0,
                                  const float* __restrict__ W1,
                                  const float* __restrict__ W2,
                                  const float* __restrict__ W3) {
    const float* Ws[4] = {W0, W1, W2, W3};
    int m   = blockIdx.y;
    int idx = blockIdx.x * blockDim.x + threadIdx.x;
    if (idx < D * D) {
        int j = idx >> 7;
        int k = idx & 127;
        g_WT[m * D * D + k * D + j] = Ws[m][idx];
    }
}

// ---------------- SGEMM (f32x2): C[M x 128] = A[M x 128] @ W^T + bias -------
// 128x128 tile, BK=8, 256 threads. Accumulator packed along row pairs.
// Thread (tx=tid&15, ty=tid>>4) owns rows [ty*8, ty*8+8) and columns
// { tx*2 + 32*jj, tx*2+1 + 32*jj : jj=0..3 } -> conflict-free B reads.
__global__ __launch_bounds__(256)
void sgemm_kernel(const float* Aext, int asel, int wbase,
                  const float* __restrict__ b0, const float* __restrict__ b1,
                  const float* __restrict__ b2,
                  float* Cext, int cbase, int M) {
    __shared__ float As[8][132];                    // As[k][row], padded
    __shared__ unsigned long long Bsd[8][128];      // Bsd[k][col] = (b,b) dup
    __shared__ float sbias[128];

    const int sel = blockIdx.y;
    const float* A    = asel ? g_agg : Aext;
    const float* Bt   = g_WT + (size_t)(wbase + sel) * D * D;
    const float* bias = (sel == 0) ? b0 : (sel == 1) ? b1 : b2;
    const int csel = cbase + sel;
    float* C = (csel == 0) ? g_q : (csel == 1) ? g_k : (csel == 2) ? g_v : Cext;

    const int tid       = threadIdx.x;
    const int block_row = blockIdx.x * 128;
    const int tx = tid & 15;
    const int ty = tid >> 4;

    const int arow = tid >> 1;          // 0..127
    const int acol = (tid & 1) << 2;    // 0 or 4
    const int brow = tid >> 5;          // 0..7
    const int bcol = (tid & 31) << 2;   // 0..124

    if (tid < 128) sbias[tid] = bias[tid];

    unsigned long long acc2[4][8];      // [row-pair p][2*jj + (0|1)]
#pragma unroll
    for (int p = 0; p < 4; p++)
#pragma unroll
        for (int j = 0; j < 8; j++) acc2[p][j] = 0ULL;

    for (int k0 = 0; k0 < D; k0 += 8) {
        // A tile: transposed store into As[k][row]
        float4 av;
        int gr = block_row + arow;
        if (gr < M) av = *(const float4*)(A + (size_t)gr * D + k0 + acol);
        else        av = make_float4(0.f, 0.f, 0.f, 0.f);
        As[acol + 0][arow] = av.x;
        As[acol + 1][arow] = av.y;
        As[acol + 2][arow] = av.z;
        As[acol + 3][arow] = av.w;

        // B tile: duplicated pairs
        float4 bv = *(const float4*)(Bt + (size_t)(k0 + brow) * D + bcol);
        ulonglong2 w0, w1;
        w0.x = dup2(bv.x); w0.y = dup2(bv.y);
        w1.x = dup2(bv.z); w1.y = dup2(bv.w);
        *(ulonglong2*)&Bsd[brow][bcol + 0] = w0;
        *(ulonglong2*)&Bsd[brow][bcol + 2] = w1;
        __syncthreads();

#pragma unroll
        for (int kk = 0; kk < 8; kk++) {
            // 4 row-pairs of A: rows ty*8 .. ty*8+7 (contiguous in As)
            ulonglong2 a01 = *(const ulonglong2*)&As[kk][ty * 8];
            ulonglong2 a23 = *(const ulonglong2*)&As[kk][ty * 8 + 4];
            unsigned long long af2[4] = {a01.x, a01.y, a23.x, a23.y};
            // 8 dup columns: 4 conflict-free 16B reads at 256B stride
            ulonglong2 q0 = *(const ulonglong2*)&Bsd[kk][tx * 2 + 0];
            ulonglong2 q1 = *(const ulonglong2*)&Bsd[kk][tx * 2 + 32];
            ulonglong2 q2 = *(const ulonglong2*)&Bsd[kk][tx * 2 + 64];
            ulonglong2 q3 = *(const ulonglong2*)&Bsd[kk][tx * 2 + 96];
            unsigned long long bf2[8] = {q0.x, q0.y, q1.x, q1.y,
                                         q2.x, q2.y, q3.x, q3.y};
#pragma unroll
            for (int p = 0; p < 4; p++)
#pragma unroll
                for (int j = 0; j < 8; j++)
                    ffma2(acc2[p][j], af2[p], bf2[j]);
        }
        __syncthreads();
    }

    // epilogue: unpack row pairs, add bias
#pragma unroll
    for (int p = 0; p < 4; p++) {
        int r0 = block_row + ty * 8 + 2 * p;
#pragma unroll
        for (int jj = 0; jj < 4; jj++) {
            float2 va = u2f(acc2[p][2 * jj + 0]);
            float2 vb = u2f(acc2[p][2 * jj + 1]);
            int colb = tx * 2 + jj * 32;
            float bx = sbias[colb], by = sbias[colb + 1];
            if (r0 < M) {
                float2 o; o.x = va.x + bx; o.y = vb.x + by;
                *(float2*)(C + (size_t)r0 * D + colb) = o;
            }
            if (r0 + 1 < M) {
                float2 o; o.x = va.y + bx; o.y = vb.y + by;
                *(float2*)(C + (size_t)(r0 + 1) * D + colb) = o;
            }
        }
    }
}

// ---------------- CSR build --------------------------------------------------
__global__ void zero_cnt_kernel(int n) {
    for (int i = blockIdx.x * blockDim.x + threadIdx.x; i < n; i += gridDim.x * blockDim.x)
        g_cnt[i] = 0;
}
__global__ void hist_kernel(const void* __restrict__ ei, int e, int n) {
    int is64 = g_is64;
    for (int idx = blockIdx.x * blockDim.x + threadIdx.x; idx < e; idx += gridDim.x * blockDim.x) {
        int c = load_edge(ei, 2 * (size_t)idx + 1, is64);
        if ((unsigned)c < (unsigned)n) atomicAdd(&g_cnt[c], 1);
    }
}
__global__ void scan_kernel(int n) {
    __shared__ int warpsum[32];
    int tid  = threadIdx.x;
    int lane = tid & 31;
    int wid  = tid >> 5;
    int carry = 0;
    for (int base = 0; base < n; base += 1024) {
        int i = base + tid;
        int x = (i < n) ? g_cnt[i] : 0;
        int s = x;
#pragma unroll
        for (int off = 1; off < 32; off <<= 1) {
            int t2 = __shfl_up_sync(0xffffffffu, s, off);
            if (lane >= off) s += t2;
        }
        if (lane == 31) warpsum[wid] = s;
        __syncthreads();
        if (wid == 0) {
            int ws = warpsum[lane];
#pragma unroll
            for (int off = 1; off < 32; off <<= 1) {
                int t2 = __shfl_up_sync(0xffffffffu, ws, off);
                if (lane >= off) ws += t2;
            }
            warpsum[lane] = ws;
        }
        __syncthreads();
        int prefix = (wid > 0) ? warpsum[wid - 1] : 0;
        int excl   = s + prefix - x;
        if (i < n) {
            g_offs[i] = carry + excl;
            g_cur[i]  = carry + excl;
        }
        int total = warpsum[31];
        __syncthreads();
        carry += total;
    }
    if (tid == 0) g_offs[n] = carry;
}
__global__ void scatter_kernel(const void* __restrict__ ei, int e, int n) {
    int is64 = g_is64;
    for (int idx = blockIdx.x * blockDim.x + threadIdx.x; idx < e; idx += gridDim.x * blockDim.x) {
        int r = load_edge(ei, 2 * (size_t)idx + 0, is64);
        int c = load_edge(ei, 2 * (size_t)idx + 1, is64);
        if ((unsigned)c < (unsigned)n && (unsigned)r < (unsigned)n) {
            int pos = atomicAdd(&g_cur[c], 1);
            if ((unsigned)pos < (unsigned)EMAX) g_src[pos] = r;
        }
    }
}

// ---------------- fused per-node attention (online softmax) ------------------
// One block of 128 threads per node; thread t owns dim t (head t/16).
// 2-deep software pipeline: src index fetched 2 ahead, k/v gathered 1 ahead.
__global__ __launch_bounds__(128)
void attn_kernel() {
    int node = blockIdx.x;
    int t    = threadIdx.x;

    float qt = g_q[(size_t)node * D + t] * 0.25f;   // 1/sqrt(HD=16)
    int beg = g_offs[node];
    int end = g_offs[node + 1];

    float m = 0.f, l = 1.f, acc = 0.f;

    int r1 = (beg + 1 < end) ? g_src[beg + 1] : 0;
    float kt = 0.f, vt = 0.f;
    if (beg < end) {
        int r0 = g_src[beg];
        kt = g_k[(size_t)r0 * D + t];
        vt = g_v[(size_t)r0 * D + t];
    }

    for (int j = beg; j < end; ++j) {
        int r2 = (j + 2 < end) ? g_src[j + 2] : 0;
        float ktn = g_k[(size_t)r1 * D + t];
        float vtn = g_v[(size_t)r1 * D + t];

        float p = qt * kt;
        p += __shfl_xor_sync(0xffffffffu, p, 8);
        p += __shfl_xor_sync(0xffffffffu, p, 4);
        p += __shfl_xor_sync(0xffffffffu, p, 2);
        p += __shfl_xor_sync(0xffffffffu, p, 1);

        float nm = fmaxf(m, p);
        float sc = __expf(m - nm);
        float pe = __expf(p - nm);
        l   = l * sc + pe;
        acc = acc * sc + pe * vt;
        m   = nm;

        kt = ktn; vt = vtn; r1 = r2;
    }

    float deg = (float)(end - beg);
    g_agg[(size_t)node * D + t] = acc / (l * fmaxf(deg, 1.f));
}

// ---------------- launch -----------------------------------------------------
extern "C" void kernel_launch(void* const* d_in, const int* in_sizes, int n_in,
                              void* d_out, int out_size) {
    const float* feats = (const float*)d_in[0];
    const void*  ei    = d_in[1];
    const float* Wq = (const float*)d_in[2];
    const float* bq = (const float*)d_in[3];
    const float* Wk = (const float*)d_in[4];
    const float* bk = (const float*)d_in[5];
    const float* Wv = (const float*)d_in[6];
    const float* bv = (const float*)d_in[7];
    const float* Wo = (const float*)d_in[8];
    const float* bo = (const float*)d_in[9];
    float* out = (float*)d_out;

    int n = in_sizes[0] / D;
    int e = in_sizes[1] / 2;
    if (n > NMAX || e > EMAX || n <= 0) return;

    // 0) detect edge_index dtype
    detect_kernel<<<1, 1>>>(ei, e);

    // 1) transpose the four weight matrices
    transpose4_kernel<<<dim3(64, 4), 256>>>(Wq, Wk, Wv, Wo);

    // 2) Q/K/V projections in ONE launch (gridDim.y = 3 fills the tail)
    int gblocks = (n + 127) / 128;
    sgemm_kernel<<<dim3(gblocks, 3), 256>>>(feats, 0, 0, bq, bk, bv,
                                            nullptr, 0, n);

    // 3) CSR by destination
    zero_cnt_kernel<<<(n + 255) / 256, 256>>>(n);
    hist_kernel<<<(e + 255) / 256, 256>>>(ei, e, n);
    scan_kernel<<<1, 1024>>>(n);
    scatter_kernel<<<(e + 255) / 256, 256>>>(ei, e, n);

    // 4) fused edge softmax + aggregation
    attn_kernel<<<n, 128>>>();

    // 5) output projection -> d_out
    sgemm_kernel<<<dim3(gblocks, 1), 256>>>(nullptr, 1, 3, bo, bo, bo,
                                            out, 3, n);
}

// round 11
// speedup vs baseline: 1.2544x; 1.0926x over previous
#include <cuda_runtime.h>
#include <cuda_bf16.h>
#include <cstdint>

#define D 128
#define NMAX 50048
#define EMAX 800000

// ---------------- scratch (static device allocations; no cudaMalloc) --------
__device__ float g_q[(size_t)NMAX * D];
__device__ float g_k[(size_t)NMAX * D];
__device__ float g_v[(size_t)NMAX * D];
__device__ float g_agg[(size_t)NMAX * D];
__device__ int   g_cnt[NMAX];
__device__ int   g_offs[NMAX + 1];
__device__ int   g_cur[NMAX];
__device__ int   g_src[EMAX];
__device__ int   g_is64;

// ---------------- edge dtype detection --------------------------------------
__global__ void detect_kernel(const void* ei, int e) {
    const long long* p = (const long long*)ei;
    int lim = (2 * e < 16) ? 2 * e : 16;
    int ok = 1;
    for (int i = 0; i < lim; ++i) {
        long long v = p[i];
        if (v < 0 || v >= NMAX) { ok = 0; break; }
    }
    g_is64 = ok;
}
__device__ __forceinline__ int load_edge(const void* ei, size_t idx, int is64) {
    if (is64) return (int)((const long long*)ei)[idx];
    return ((const int*)ei)[idx];
}

// ---------------- mma.sync bf16 helpers (base ISA, sm_80+) -------------------
__device__ __forceinline__ uint32_t smem_u32(const void* p) {
    uint32_t a;
    asm("{ .reg .u64 t; cvta.to.shared.u64 t, %1; cvt.u32.u64 %0, t; }" : "=r"(a) : "l"(p));
    return a;
}
__device__ __forceinline__ void ldm_x4(uint32_t r[4], uint32_t addr) {
    asm volatile("ldmatrix.sync.aligned.m8n8.x4.shared.b16 {%0,%1,%2,%3}, [%4];"
                 : "=r"(r[0]), "=r"(r[1]), "=r"(r[2]), "=r"(r[3]) : "r"(addr));
}
__device__ __forceinline__ void mma_bf16(float d[4], const uint32_t a[4], const uint32_t b[2]) {
    asm volatile(
        "mma.sync.aligned.m16n8k16.row.col.f32.bf16.bf16.f32 "
        "{%0,%1,%2,%3}, {%4,%5,%6,%7}, {%8,%9}, {%0,%1,%2,%3};"
        : "+f"(d[0]), "+f"(d[1]), "+f"(d[2]), "+f"(d[3])
        : "r"(a[0]), "r"(a[1]), "r"(a[2]), "r"(a[3]), "r"(b[0]), "r"(b[1]));
}

// split fp32x4 -> bf16 hi (packed 2x u32) + bf16 lo
__device__ __forceinline__ void split4(float4 x, uint2& h, uint2& l) {
    __nv_bfloat16 hx = __float2bfloat16_rn(x.x);
    __nv_bfloat16 hy = __float2bfloat16_rn(x.y);
    __nv_bfloat16 hz = __float2bfloat16_rn(x.z);
    __nv_bfloat16 hw = __float2bfloat16_rn(x.w);
    __nv_bfloat16 lx = __float2bfloat16_rn(x.x - __bfloat162float(hx));
    __nv_bfloat16 ly = __float2bfloat16_rn(x.y - __bfloat162float(hy));
    __nv_bfloat16 lz = __float2bfloat16_rn(x.z - __bfloat162float(hz));
    __nv_bfloat16 lw = __float2bfloat16_rn(x.w - __bfloat162float(hw));
    h.x = (uint32_t)__bfloat16_as_ushort(hx) | ((uint32_t)__bfloat16_as_ushort(hy) << 16);
    h.y = (uint32_t)__bfloat16_as_ushort(hz) | ((uint32_t)__bfloat16_as_ushort(hw) << 16);
    l.x = (uint32_t)__bfloat16_as_ushort(lx) | ((uint32_t)__bfloat16_as_ushort(ly) << 16);
    l.y = (uint32_t)__bfloat16_as_ushort(lz) | ((uint32_t)__bfloat16_as_ushort(lw) << 16);
}

// ---------------- HMMA 3xBF16 GEMM: C[M x 128] = A @ W^T + bias -------------
// CTA: 128x128 tile, whole K=128 in smem (bf16 hi/lo for A and B).
// Rows padded to 136 bf16 (272B) -> ldmatrix phases hit all 32 banks.
// 8 warps: warp w -> (wm = w&3) rows [wm*32,+32), (wn = w>>2) cols [wn*64,+64).
#define ROWB 272                        // bytes per padded row
#define OFF_AHI 0
#define OFF_ALO (128 * ROWB)            // 34816
#define OFF_BHI (2 * 128 * ROWB)
#define OFF_BLO (3 * 128 * ROWB)
#define OFF_BIAS (4 * 128 * ROWB)       // 139264
#define GEMM_SMEM (OFF_BIAS + 512)      // 139776

__global__ __launch_bounds__(256, 1)
void hmma_gemm_kernel(const float* Aext, int asel,
                      const float* __restrict__ w0, const float* __restrict__ w1,
                      const float* __restrict__ w2,
                      const float* __restrict__ b0, const float* __restrict__ b1,
                      const float* __restrict__ b2,
                      float* Cext, int cbase, int M) {
    extern __shared__ char smem[];
    const uint32_t sb = smem_u32(smem);

    const int sel = blockIdx.y;
    const float* A    = asel ? g_agg : Aext;
    const float* Bw   = (sel == 0) ? w0 : (sel == 1) ? w1 : w2;
    const float* bias = (sel == 0) ? b0 : (sel == 1) ? b1 : b2;
    const int csel = cbase + sel;
    float* C = (csel == 0) ? g_q : (csel == 1) ? g_k : (csel == 2) ? g_v : Cext;

    const int tid  = threadIdx.x;
    const int wid  = tid >> 5;
    const int lane = tid & 31;
    const int block_row = blockIdx.x * 128;
    const int wm = wid & 3;     // M group (rows wm*32..+32)
    const int wn = wid >> 2;    // N group (cols wn*64..+64)

    // ---- load + split A and B into smem ----
    if (tid < 128) *(float*)(smem + OFF_BIAS + tid * 4) = bias[tid];
    for (int i = tid; i < 4096; i += 256) {          // 128 rows x 32 float4
        int row = i >> 5;
        int k4  = (i & 31) << 2;
        uint32_t sboff = (uint32_t)row * ROWB + k4 * 2;
        // A (guarded)
        float4 x = make_float4(0.f, 0.f, 0.f, 0.f);
        int gr = block_row + row;
        if (gr < M) x = *(const float4*)(A + (size_t)gr * D + k4);
        uint2 h, l;
        split4(x, h, l);
        *(uint2*)(smem + OFF_AHI + sboff) = h;
        *(uint2*)(smem + OFF_ALO + sboff) = l;
        // B = W[n][k] row-major (exactly the "col" operand layout)
        float4 b = *(const float4*)(Bw + (size_t)row * D + k4);
        split4(b, h, l);
        *(uint2*)(smem + OFF_BHI + sboff) = h;
        *(uint2*)(smem + OFF_BLO + sboff) = l;
    }
    __syncthreads();

    // ---- mainloop: 8 k16-steps, 3-term bf16 compensation ----
    float acc[2][8][4];
#pragma unroll
    for (int mt = 0; mt < 2; mt++)
#pragma unroll
        for (int nt = 0; nt < 8; nt++)
#pragma unroll
            for (int c = 0; c < 4; c++) acc[mt][nt][c] = 0.f;

    const int li = lane & 7;
    const int lq = lane >> 3;

    for (int ks = 0; ks < 8; ks++) {
        const int k0 = ks * 16;
        // A fragments (hi & lo) for both m16 tiles
        uint32_t ah[2][4], al[2][4];
#pragma unroll
        for (int mt = 0; mt < 2; mt++) {
            // quadrants: qd0:(m+i,k0) qd1:(m+8+i,k0) qd2:(m+i,k0+8) qd3:(m+8+i,k0+8)
            int row = wm * 32 + mt * 16 + li + (lq & 1) * 8;
            int col = k0 + (lq >> 1) * 8;
            uint32_t off = (uint32_t)row * ROWB + col * 2;
            ldm_x4(ah[mt], sb + OFF_AHI + off);
            ldm_x4(al[mt], sb + OFF_ALO + off);
        }
        // B pairs: np covers n-tiles {2np, 2np+1}
#pragma unroll
        for (int np = 0; np < 4; np++) {
            // quadrants: qd0:(n+i,k0) qd1:(n+i,k0+8) qd2:(n+8+i,k0) qd3:(n+8+i,k0+8)
            int row = wn * 64 + np * 16 + li + (lq >> 1) * 8;
            int col = k0 + (lq & 1) * 8;
            uint32_t off = (uint32_t)row * ROWB + col * 2;
            uint32_t bh[4], bl[4];
            ldm_x4(bh, sb + OFF_BHI + off);
            ldm_x4(bl, sb + OFF_BLO + off);
#pragma unroll
            for (int mt = 0; mt < 2; mt++) {
                mma_bf16(acc[mt][2 * np + 0], ah[mt], &bh[0]);
                mma_bf16(acc[mt][2 * np + 0], ah[mt], &bl[0]);
                mma_bf16(acc[mt][2 * np + 0], al[mt], &bh[0]);
                mma_bf16(acc[mt][2 * np + 1], ah[mt], &bh[2]);
                mma_bf16(acc[mt][2 * np + 1], ah[mt], &bl[2]);
                mma_bf16(acc[mt][2 * np + 1], al[mt], &bh[2]);
            }
        }
    }

    // ---- epilogue: +bias, store ----
    const int tg = lane >> 2;        // 0..7
    const int tc = (lane & 3) * 2;   // 0,2,4,6
#pragma unroll
    for (int mt = 0; mt < 2; mt++) {
        int r0 = block_row + wm * 32 + mt * 16 + tg;
#pragma unroll
        for (int nt = 0; nt < 8; nt++) {
            int col = wn * 64 + nt * 8 + tc;
            float bx = *(float*)(smem + OFF_BIAS + col * 4);
            float by = *(float*)(smem + OFF_BIAS + (col + 1) * 4);
            if (r0 < M) {
                float2 o; o.x = acc[mt][nt][0] + bx; o.y = acc[mt][nt][1] + by;
                *(float2*)(C + (size_t)r0 * D + col) = o;
            }
            if (r0 + 8 < M) {
                float2 o; o.x = acc[mt][nt][2] + bx; o.y = acc[mt][nt][3] + by;
                *(float2*)(C + (size_t)(r0 + 8) * D + col) = o;
            }
        }
    }
}

// ---------------- CSR build --------------------------------------------------
__global__ void zero_cnt_kernel(int n) {
    for (int i = blockIdx.x * blockDim.x + threadIdx.x; i < n; i += gridDim.x * blockDim.x)
        g_cnt[i] = 0;
}
__global__ void hist_kernel(const void* __restrict__ ei, int e, int n) {
    int is64 = g_is64;
    for (int idx = blockIdx.x * blockDim.x + threadIdx.x; idx < e; idx += gridDim.x * blockDim.x) {
        int c = load_edge(ei, 2 * (size_t)idx + 1, is64);
        if ((unsigned)c < (unsigned)n) atomicAdd(&g_cnt[c], 1);
    }
}
__global__ void scan_kernel(int n) {
    __shared__ int warpsum[32];
    int tid  = threadIdx.x;
    int lane = tid & 31;
    int wid  = tid >> 5;
    int carry = 0;
    for (int base = 0; base < n; base += 1024) {
        int i = base + tid;
        int x = (i < n) ? g_cnt[i] : 0;
        int s = x;
#pragma unroll
        for (int off = 1; off < 32; off <<= 1) {
            int t2 = __shfl_up_sync(0xffffffffu, s, off);
            if (lane >= off) s += t2;
        }
        if (lane == 31) warpsum[wid] = s;
        __syncthreads();
        if (wid == 0) {
            int ws = warpsum[lane];
#pragma unroll
            for (int off = 1; off < 32; off <<= 1) {
                int t2 = __shfl_up_sync(0xffffffffu, ws, off);
                if (lane >= off) ws += t2;
            }
            warpsum[lane] = ws;
        }
        __syncthreads();
        int prefix = (wid > 0) ? warpsum[wid - 1] : 0;
        int excl   = s + prefix - x;
        if (i < n) {
            g_offs[i] = carry + excl;
            g_cur[i]  = carry + excl;
        }
        int total = warpsum[31];
        __syncthreads();
        carry += total;
    }
    if (tid == 0) g_offs[n] = carry;
}
__global__ void scatter_kernel(const void* __restrict__ ei, int e, int n) {
    int is64 = g_is64;
    for (int idx = blockIdx.x * blockDim.x + threadIdx.x; idx < e; idx += gridDim.x * blockDim.x) {
        int r = load_edge(ei, 2 * (size_t)idx + 0, is64);
        int c = load_edge(ei, 2 * (size_t)idx + 1, is64);
        if ((unsigned)c < (unsigned)n && (unsigned)r < (unsigned)n) {
            int pos = atomicAdd(&g_cur[c], 1);
            if ((unsigned)pos < (unsigned)EMAX) g_src[pos] = r;
        }
    }
}

// ---------------- fused per-node attention (online softmax) ------------------
__global__ __launch_bounds__(128)
void attn_kernel() {
    int node = blockIdx.x;
    int t    = threadIdx.x;

    float qt = g_q[(size_t)node * D + t] * 0.25f;   // 1/sqrt(HD=16)
    int beg = g_offs[node];
    int end = g_offs[node + 1];

    float m = 0.f, l = 1.f, acc = 0.f;

    int r1 = (beg + 1 < end) ? g_src[beg + 1] : 0;
    float kt = 0.f, vt = 0.f;
    if (beg < end) {
        int r0 = g_src[beg];
        kt = g_k[(size_t)r0 * D + t];
        vt = g_v[(size_t)r0 * D + t];
    }

    for (int j = beg; j < end; ++j) {
        int r2 = (j + 2 < end) ? g_src[j + 2] : 0;
        float ktn = g_k[(size_t)r1 * D + t];
        float vtn = g_v[(size_t)r1 * D + t];

        float p = qt * kt;
        p += __shfl_xor_sync(0xffffffffu, p, 8);
        p += __shfl_xor_sync(0xffffffffu, p, 4);
        p += __shfl_xor_sync(0xffffffffu, p, 2);
        p += __shfl_xor_sync(0xffffffffu, p, 1);

        float nm = fmaxf(m, p);
        float sc = __expf(m - nm);
        float pe = __expf(p - nm);
        l   = l * sc + pe;
        acc = acc * sc + pe * vt;
        m   = nm;

        kt = ktn; vt = vtn; r1 = r2;
    }

    float deg = (float)(end - beg);
    g_agg[(size_t)node * D + t] = acc / (l * fmaxf(deg, 1.f));
}

// ---------------- launch -----------------------------------------------------
extern "C" void kernel_launch(void* const* d_in, const int* in_sizes, int n_in,
                              void* d_out, int out_size) {
    const float* feats = (const float*)d_in[0];
    const void*  ei    = d_in[1];
    const float* Wq = (const float*)d_in[2];
    const float* bq = (const float*)d_in[3];
    const float* Wk = (const float*)d_in[4];
    const float* bk = (const float*)d_in[5];
    const float* Wv = (const float*)d_in[6];
    const float* bv = (const float*)d_in[7];
    const float* Wo = (const float*)d_in[8];
    const float* bo = (const float*)d_in[9];
    float* out = (float*)d_out;

    int n = in_sizes[0] / D;
    int e = in_sizes[1] / 2;
    if (n > NMAX || e > EMAX || n <= 0) return;

    cudaFuncSetAttribute(hmma_gemm_kernel,
                         cudaFuncAttributeMaxDynamicSharedMemorySize, GEMM_SMEM);

    // 0) detect edge_index dtype
    detect_kernel<<<1, 1>>>(ei, e);

    // 1) Q/K/V projections in ONE launch (gridDim.y = 3)
    int gblocks = (n + 127) / 128;
    hmma_gemm_kernel<<<dim3(gblocks, 3), 256, GEMM_SMEM>>>(
        feats, 0, Wq, Wk, Wv, bq, bk, bv, nullptr, 0, n);

    // 2) CSR by destination
    zero_cnt_kernel<<<(n + 255) / 256, 256>>>(n);
    hist_kernel<<<(e + 255) / 256, 256>>>(ei, e, n);
    scan_kernel<<<1, 1024>>>(n);
    scatter_kernel<<<(e + 255) / 256, 256>>>(ei, e, n);

    // 3) fused edge softmax + aggregation
    attn_kernel<<<n, 128>>>();

    // 4) output projection -> d_out
    hmma_gemm_kernel<<<dim3(gblocks, 1), 256, GEMM_SMEM>>>(
        nullptr, 1, Wo, Wo, Wo, bo, bo, bo, out, 3, n);
}